// round 6
// baseline (speedup 1.0000x reference)
#include <cuda_runtime.h>
#include <cuda_bf16.h>
#include <math.h>
#include <stdint.h>

#define BN    1024
#define FEATN 512
#define HN    256
#define TI    4
#define TJ    16
#define KCQ   32        // k per chunk (int8 path)
#define NCHQ  16        // 512/32 chunks per pass
#define RSQ   48        // padded row stride bytes (conflict-free ldmatrix)

// ---- smem layout ----
#define OFF_XI   0               // 4 x 512 f32  = 8192
#define OFF_XJ   8192            // 16 x 512 f32 = 32768
#define OFF_ST   40960           // 2 stages x 18432
#define STAGE_SZ 18432
#define ST_AH    0               // 64 x 48 = 3072
#define ST_AL    3072
#define ST_BH    6144            // 128 x 48 = 6144
#define ST_BL    12288
#define OFF_EPI  77824           // float4 per col: 256 x 16 = 4096
#define OFF_RED  81920           // 64 x 4 floats
#define OFF_PART 82944           // 64 floats
#define SMEM_TOTAL 83200

// quantized W1 digit planes: [plane][chunk][nhalf][128 rows x 48B]
__device__ char  g_Bq[2][NCHQ][2][6144];
__device__ float g_Amax, g_sa, g_sb, g_c16, g_c8;

__device__ __forceinline__ uint32_t smem_u32(const void* p) {
    uint32_t a;
    asm("{ .reg .u64 t; cvta.to.shared.u64 t, %1; cvt.u32.u64 %0, t; }" : "=r"(a) : "l"(p));
    return a;
}

#define LDSM_X4(r0,r1,r2,r3,addr) \
    asm volatile("ldmatrix.sync.aligned.m8n8.x4.shared.b16 {%0,%1,%2,%3}, [%4];" \
        : "=r"(r0), "=r"(r1), "=r"(r2), "=r"(r3) : "r"(addr))

#define IMMA(d, a, b0, b1) \
    asm volatile("mma.sync.aligned.m16n8k32.row.col.s32.s8.s8.s32 " \
        "{%0,%1,%2,%3}, {%4,%5,%6,%7}, {%8,%9}, {%0,%1,%2,%3};" \
        : "+r"((d)[0]), "+r"((d)[1]), "+r"((d)[2]), "+r"((d)[3]) \
        : "r"((a)[0]), "r"((a)[1]), "r"((a)[2]), "r"((a)[3]), "r"(b0), "r"(b1))

#define CP_ASYNC16(dst, src) \
    asm volatile("cp.async.cg.shared.global [%0], [%1], 16;" :: "r"(dst), "l"(src))
#define CP_COMMIT() asm volatile("cp.async.commit_group;" ::: "memory")
#define CP_WAIT0()  asm volatile("cp.async.wait_group 0;" ::: "memory")

// branch-free GELU: erf via A&S 7.1.26 (abs err < 1.5e-7)
__device__ __forceinline__ float gelu_erf(float x) {
    float u = 0.70710678118654752f * x;
    float a = fabsf(u);
    float den = fmaf(0.3275911f, a, 1.0f);
    float t;
    asm("rcp.approx.f32 %0, %1;" : "=f"(t) : "f"(den));
    float p = fmaf(fmaf(fmaf(fmaf(1.061405429f, t, -1.453152027f), t,
                             1.421413741f), t, -0.284496736f), t, 0.254829592f) * t;
    float e;
    asm("ex2.approx.f32 %0, %1;" : "=f"(e) : "f"(-a * a * 1.4426950408889634f));
    float erfa = fmaf(-p, e, 1.0f);
    float erfu = copysignf(erfa, u);
    return 0.5f * x * (1.0f + erfu);
}

// ---------------- scale kernels ----------------
__global__ void kAmax(const float* __restrict__ X) {
    __shared__ float red[512];
    int t = threadIdx.x;                 // feature
    float mx = -1e30f, mn = 1e30f;
    for (int i = 0; i < BN; i++) {
        float v = X[i * FEATN + t];
        mx = fmaxf(mx, v); mn = fminf(mn, v);
    }
    red[t] = mx - mn;
    __syncthreads();
    for (int off = 256; off > 0; off >>= 1) {
        if (t < off) red[t] = fmaxf(red[t], red[t + off]);
        __syncthreads();
    }
    if (t == 0) g_Amax = red[0];
}

__global__ void kWmaxScales(const float* __restrict__ W1) {
    __shared__ float red[512];
    int t = threadIdx.x;
    float m = 0.0f;
    for (int r = 0; r < 256; r++)
        m = fmaxf(m, fabsf(W1[t + 512 * r]));
    red[t] = m;
    __syncthreads();
    for (int off = 256; off > 0; off >>= 1) {
        if (t < off) red[t] = fmaxf(red[t], red[t + off]);
        __syncthreads();
    }
    if (t == 0) {
        float sa = 32512.0f / fmaxf(g_Amax, 1e-20f);
        float sb = 32512.0f / fmaxf(red[0], 1e-20f);
        g_sa = sa; g_sb = sb;
        float inv = 1.0f / (sa * sb);
        g_c16 = 65536.0f * inv;
        g_c8  = 256.0f * inv;
    }
}

// ---------------- prep: quantize W1[0:512] -> s8 digit planes ----------------
__global__ void prep_q(const float* __restrict__ W1) {
    int k = blockIdx.x;       // 0..511
    int n = threadIdx.x;      // 0..255
    float sb = g_sb;
    float w = W1[k * HN + n];
    int b16 = __float2int_rn(w * sb);
    int bh = (b16 + 128) >> 8;
    int bl = b16 - (bh << 8);
    int c = k >> 5, kk = k & 31;
    int nh = n >> 7, nl = n & 127;
    g_Bq[0][c][nh][nl * RSQ + kk] = (char)bh;
    g_Bq[1][c][nh][nl * RSQ + kk] = (char)bl;
    if (kk < 16) {   // zero pad bytes 32..47
        g_Bq[0][c][nh][nl * RSQ + 32 + kk] = 0;
        g_Bq[1][c][nh][nl * RSQ + 32 + kk] = 0;
    }
}

// ---------------- A build: quantize |xi - xj| into s8 digit planes ----------
__device__ __forceinline__ void build_A(char* SB, uint32_t stg_off, int c, int tid, float sa) {
    int p  = tid >> 2;            // pair 0..63
    int kq = (tid & 3) * 8;       // k offset 0,8,16,24
    const float* xi = (const float*)(SB + OFF_XI) + (p >> 4) * 512 + c * KCQ + kq;
    const float* xj = (const float*)(SB + OFF_XJ) + (p & 15) * 512 + c * KCQ + kq;
    float4 xa = *(const float4*)xi, xb = *(const float4*)(xi + 4);
    float4 ya = *(const float4*)xj, yb = *(const float4*)(xj + 4);
    float dv[8] = { fabsf(xa.x-ya.x), fabsf(xa.y-ya.y), fabsf(xa.z-ya.z), fabsf(xa.w-ya.w),
                    fabsf(xb.x-yb.x), fabsf(xb.y-yb.y), fabsf(xb.z-yb.z), fabsf(xb.w-yb.w) };
    uint32_t hw[2] = {0, 0}, lw[2] = {0, 0};
#pragma unroll
    for (int u = 0; u < 8; u++) {
        int q = __float2int_rn(dv[u] * sa);
        int ah = (q + 128) >> 8;
        int al = q - (ah << 8);
        hw[u >> 2] |= ((uint32_t)(uint8_t)(char)ah) << ((u & 3) * 8);
        lw[u >> 2] |= ((uint32_t)(uint8_t)(char)al) << ((u & 3) * 8);
    }
    uint32_t off = (uint32_t)(p * RSQ + kq);
    *(uint2*)(SB + stg_off + ST_AH + off) = make_uint2(hw[0], hw[1]);
    *(uint2*)(SB + stg_off + ST_AL + off) = make_uint2(lw[0], lw[1]);
}

// ---------------- main scorer: 256 thr, M64 x (2 passes x N128), 2 CTAs/SM --
__global__ __launch_bounds__(256, 2)
void scorer_mma(const float* __restrict__ X,
                const float* __restrict__ logits,
                const float* __restrict__ b1,
                const float* __restrict__ W1,
                const float* __restrict__ W2,
                const float* __restrict__ b2,
                float* __restrict__ hs)
{
    const int ib = blockIdx.y;           // 0..255 (TI=4)
    const int jb = blockIdx.x;           // 0..63  (TJ=16)
    if (jb * TJ + (TJ - 1) < ib * TI) return;

    extern __shared__ __align__(128) char SB[];
    const uint32_t sb = smem_u32(SB);

    const int tid  = threadIdx.x;
    const int wid  = tid >> 5;
    const int lane = tid & 31;
    const int i0 = ib * TI, j0 = jb * TJ;

    // 8 warps: 2 M-groups x 4 N-groups; warp covers M32 x N32 (per pass)
    const int mg = wid >> 2, ng = wid & 3;
    const int m0 = mg * 32;

    const float sa  = g_sa;
    const float c16 = g_c16;
    const float c8  = g_c8;

    // ---- preload X rows + epilogue constants ----
    {
        float4* dXi = (float4*)(SB + OFF_XI);
        float4* dXj = (float4*)(SB + OFF_XJ);
#pragma unroll
        for (int r = 0; r < 2; r++) {
            int idx = tid + 256 * r;              // 512 float4
            dXi[idx] = ((const float4*)X)[(i0 + (idx >> 7)) * 128 + (idx & 127)];
        }
#pragma unroll
        for (int r = 0; r < 8; r++) {
            int idx = tid + 256 * r;              // 2048 float4
            dXj[idx] = ((const float4*)X)[(j0 + (idx >> 7)) * 128 + (idx & 127)];
        }
        float4* e = (float4*)(SB + OFF_EPI);
        e[tid] = make_float4(W1[512 * HN + tid], W1[513 * HN + tid],
                             b1[tid], W2[tid]);
    }
    __syncthreads();

    // ---- label coefficients for this thread's 4 row-slots ----
    float cc0[4], cc1[4];
#pragma unroll
    for (int slot = 0; slot < 4; slot++) {
        int p = m0 + (slot >> 1) * 16 + (slot & 1) * 8 + (lane >> 2);
        int gi = i0 + (p >> 4), gj = j0 + (p & 15);
        float pi = 1.0f / (1.0f + expf(logits[gi*2+1] - logits[gi*2]));
        float pj = 1.0f / (1.0f + expf(logits[gj*2+1] - logits[gj*2]));
        cc0[slot] = pi * pj;
        cc1[slot] = (1.0f - pi) * (1.0f - pj);
    }

    // ---- prologue: vchunk 0 (chunk 0, nh 0) into stage 0 ----
    {
        const char* srcBase = &g_Bq[0][0][0][0];
#pragma unroll
        for (int r = 0; r < 3; r++) {
            int idx = tid + 256 * r;              // 768 x 16B
            int plane = (idx >= 384);
            int off = idx - plane * 384;
            const char* src = srcBase + plane * (NCHQ * 2 * 6144) + off * 16;
            CP_ASYNC16(sb + OFF_ST + ST_BH + plane * 6144 + off * 16, src);
        }
        build_A(SB, OFF_ST, 0, tid, sa);
        CP_COMMIT();
    }

    // ---- per-thread ldmatrix base offsets ----
    const uint32_t aBase = (uint32_t)((m0 + (lane & 7) + ((lane >> 3) & 1) * 8) * RSQ
                                      + ((lane >> 4) & 1) * 16);
    const uint32_t bBase = (uint32_t)((ng * 32 + (lane & 7) + ((lane >> 4) & 1) * 8) * RSQ
                                      + ((lane >> 3) & 1) * 16);

    int acc_h[2][4][4], acc_m[2][4][4];
#pragma unroll
    for (int a = 0; a < 2; a++)
#pragma unroll
        for (int g = 0; g < 4; g++)
#pragma unroll
            for (int r = 0; r < 4; r++) { acc_h[a][g][r] = 0; acc_m[a][g][r] = 0; }

    // ---- main loop: 32 vchunks = 2 passes x 16 k-chunks ----
    for (int vc = 0; vc < 2 * NCHQ; vc++) {
        const int s = vc & 1;
        CP_WAIT0();
        __syncthreads();

        if (vc + 1 < 2 * NCHQ) {
            int c2 = (vc + 1) & (NCHQ - 1);
            int nh2 = (vc + 1) >> 4;
            const char* srcBase = &g_Bq[0][c2][nh2][0];
            uint32_t dstB = sb + OFF_ST + (s ^ 1) * STAGE_SZ + ST_BH;
#pragma unroll
            for (int r = 0; r < 3; r++) {
                int idx = tid + 256 * r;
                int plane = (idx >= 384);
                int off = idx - plane * 384;
                const char* src = srcBase + plane * (NCHQ * 2 * 6144) + off * 16;
                CP_ASYNC16(dstB + plane * 6144 + off * 16, src);
            }
            build_A(SB, OFF_ST + (s ^ 1) * STAGE_SZ, c2, tid, sa);
            CP_COMMIT();
        }

        const uint32_t stg = sb + OFF_ST + s * STAGE_SZ;
        uint32_t ahf[2][4], alf[2][4];
#pragma unroll
        for (int m2 = 0; m2 < 2; m2++) {
            uint32_t aa = stg + ST_AH + aBase + m2 * (16 * RSQ);
            LDSM_X4(ahf[m2][0], ahf[m2][1], ahf[m2][2], ahf[m2][3], aa);
            LDSM_X4(alf[m2][0], alf[m2][1], alf[m2][2], alf[m2][3], aa + (ST_AL - ST_AH));
        }
#pragma unroll
        for (int h = 0; h < 2; h++) {
            uint32_t ba = stg + ST_BH + bBase + h * (16 * RSQ);
            uint32_t bh4[4], bl4[4];
            LDSM_X4(bh4[0], bh4[1], bh4[2], bh4[3], ba);
            LDSM_X4(bl4[0], bl4[1], bl4[2], bl4[3], ba + (ST_BL - ST_BH));
#pragma unroll
            for (int gg = 0; gg < 2; gg++) {
                int g = h * 2 + gg;
#pragma unroll
                for (int m2 = 0; m2 < 2; m2++) {
                    IMMA(acc_h[m2][g], ahf[m2], bh4[gg*2], bh4[gg*2+1]);
                    IMMA(acc_m[m2][g], ahf[m2], bl4[gg*2], bl4[gg*2+1]);
                    IMMA(acc_m[m2][g], alf[m2], bh4[gg*2], bh4[gg*2+1]);
                }
            }
        }

        // ---- per-pass epilogue ----
        if ((vc & (NCHQ - 1)) == NCHQ - 1) {
            int pass = vc >> 4;
            const float4* epi4 = (const float4*)(SB + OFF_EPI);
            float sacc[4] = {0.0f, 0.0f, 0.0f, 0.0f};
#pragma unroll
            for (int g = 0; g < 4; g++)
#pragma unroll
                for (int e = 0; e < 2; e++) {
                    int col = pass * 128 + ng * 32 + g * 8 + (lane & 3) * 2 + e;
                    float4 w = epi4[col];
#pragma unroll
                    for (int slot = 0; slot < 4; slot++) {
                        int m2 = slot >> 1, rr = slot & 1;
                        float x = c16 * (float)acc_h[m2][g][rr*2+e]
                                + c8  * (float)acc_m[m2][g][rr*2+e]
                                + cc0[slot] * w.x + cc1[slot] * w.y + w.z;
                        sacc[slot] = fmaf(gelu_erf(x), w.w, sacc[slot]);
                    }
                }
#pragma unroll
            for (int slot = 0; slot < 4; slot++) {
                sacc[slot] += __shfl_xor_sync(0xffffffffu, sacc[slot], 1);
                sacc[slot] += __shfl_xor_sync(0xffffffffu, sacc[slot], 2);
            }
            float* red = (float*)(SB + OFF_RED);
            if ((lane & 3) == 0) {
#pragma unroll
                for (int slot = 0; slot < 4; slot++) {
                    int p = m0 + (slot >> 1) * 16 + (slot & 1) * 8 + (lane >> 2);
                    red[p * 4 + ng] = sacc[slot];
                }
            }
            __syncthreads();
            float* part = (float*)(SB + OFF_PART);
            if (tid < 64) {
                float4 r4 = *(const float4*)&red[tid * 4];
                float ssum = (r4.x + r4.y) + (r4.z + r4.w);
                if (pass == 0) {
                    part[tid] = ssum;
                } else {
                    float tot = part[tid] + ssum + b2[0];
                    float sc = 1.0f / (1.0f + expf(-tot));
                    int gi = i0 + (tid >> 4), gj = j0 + (tid & 15);
                    hs[gi * BN + gj] = sc;
                    hs[gj * BN + gi] = sc;
                }
            }
            if (pass == 0) {
#pragma unroll
                for (int a = 0; a < 2; a++)
#pragma unroll
                    for (int g = 0; g < 4; g++)
#pragma unroll
                        for (int r = 0; r < 4; r++) { acc_h[a][g][r] = 0; acc_m[a][g][r] = 0; }
            }
        }
    }
}

// ---------------- row softmax of adj + 5*log(hs + 1e-8) ----------------
__global__ __launch_bounds__(256)
void softmax_kernel(const float* __restrict__ adj,
                    const float* __restrict__ hs,
                    float* __restrict__ out)
{
    const int row = blockIdx.x;
    const int tid = threadIdx.x;
    __shared__ float red[256];

    float v[4];
    float mx = -3.4e38f;
#pragma unroll
    for (int u = 0; u < 4; u++) {
        int j = tid + 256 * u;
        float s = hs[row * BN + j];
        v[u] = adj[row * BN + j] + 5.0f * logf(s + 1e-8f);
        mx = fmaxf(mx, v[u]);
    }
    red[tid] = mx;
    __syncthreads();
    for (int off = 128; off > 0; off >>= 1) {
        if (tid < off) red[tid] = fmaxf(red[tid], red[tid + off]);
        __syncthreads();
    }
    mx = red[0];
    __syncthreads();

    float sum = 0.0f;
#pragma unroll
    for (int u = 0; u < 4; u++) {
        v[u] = expf(v[u] - mx);
        sum += v[u];
    }
    red[tid] = sum;
    __syncthreads();
    for (int off = 128; off > 0; off >>= 1) {
        if (tid < off) red[tid] += red[tid + off];
        __syncthreads();
    }
    float inv = 1.0f / red[0];
#pragma unroll
    for (int u = 0; u < 4; u++) {
        int j = tid + 256 * u;
        out[row * BN + j] = v[u] * inv;
    }
}

extern "C" void kernel_launch(void* const* d_in, const int* in_sizes, int n_in,
                              void* d_out, int out_size)
{
    const float* X      = (const float*)d_in[0];   // [1024, 512]
    const float* logits = (const float*)d_in[1];   // [1024, 2]
    const float* adj    = (const float*)d_in[2];   // [1024, 1024]
    const float* W1     = (const float*)d_in[3];   // [514, 256]
    const float* b1     = (const float*)d_in[4];   // [256]
    const float* W2     = (const float*)d_in[5];   // [256, 1]
    const float* b2     = (const float*)d_in[6];   // [1]

    float* out = (float*)d_out;          // [adj_refined (1M) | h_scores (1M)]
    float* hs  = out + BN * BN;

    static int configured = 0;
    if (!configured) {
        cudaFuncSetAttribute(scorer_mma, cudaFuncAttributeMaxDynamicSharedMemorySize, SMEM_TOTAL);
        configured = 1;
    }

    kAmax<<<1, 512>>>(X);
    kWmaxScales<<<1, 512>>>(W1);
    prep_q<<<FEATN, HN>>>(W1);
    dim3 grid(BN / TJ, BN / TI);   // (64, 256)
    scorer_mma<<<grid, 256, SMEM_TOTAL>>>(X, logits, b1, W1, W2, b2, hs);
    softmax_kernel<<<BN, 256>>>(adj, hs, out);
}

// round 7
// speedup vs baseline: 3.6760x; 3.6760x over previous
#include <cuda_runtime.h>
#include <cuda_fp16.h>
#include <math.h>
#include <stdint.h>

#define BN    1024
#define FEATN 512
#define HN    256
#define TI    4
#define TJ    16
#define KC    16       // k per chunk
#define NCH   32       // 512/16
#define RSB   48       // padded row stride bytes: conflict-free ldmatrix

// ---- smem layout (bytes from 128B-aligned dynamic base) ----
#define OFF_XI   0               // 4 x 512 f32  = 8192
#define OFF_XJ   8192            // 16 x 512 f32 = 32768
#define OFF_ST   40960           // 2 stages x 18432
#define STAGE_SZ 18432
#define ST_AH    0               // A_h 64x48 = 3072
#define ST_AL    3072            // A_l 64x48 = 3072
#define ST_B     6144            // B   256x48 = 12288
#define OFF_EPI  77824           // float4 per col: 256 x 16 = 4096
#define OFF_RED  81920           // 64 x 4 floats = 1024
#define SMEM_TOTAL 83200

// W1[0:512] rounded to fp16, transposed [N,K], 48B-padded rows: [chunk][768 uint4]
__device__ uint4 g_W1h[NCH][768];

__device__ __forceinline__ uint32_t smem_u32(const void* p) {
    uint32_t a;
    asm("{ .reg .u64 t; cvta.to.shared.u64 t, %1; cvt.u32.u64 %0, t; }" : "=r"(a) : "l"(p));
    return a;
}

#define LDSM_X4(r0,r1,r2,r3,addr) \
    asm volatile("ldmatrix.sync.aligned.m8n8.x4.shared.b16 {%0,%1,%2,%3}, [%4];" \
        : "=r"(r0), "=r"(r1), "=r"(r2), "=r"(r3) : "r"(addr))

#define MMAH(d, a0,a1,a2,a3, b0,b1) \
    asm volatile("mma.sync.aligned.m16n8k16.row.col.f32.f16.f16.f32 " \
        "{%0,%1,%2,%3}, {%4,%5,%6,%7}, {%8,%9}, {%0,%1,%2,%3};" \
        : "+f"((d)[0]), "+f"((d)[1]), "+f"((d)[2]), "+f"((d)[3]) \
        : "r"(a0), "r"(a1), "r"(a2), "r"(a3), "r"(b0), "r"(b1))

#define CP_ASYNC16(dst, src) \
    asm volatile("cp.async.cg.shared.global [%0], [%1], 16;" :: "r"(dst), "l"(src))
#define CP_COMMIT() asm volatile("cp.async.commit_group;" ::: "memory")
#define CP_WAIT0()  asm volatile("cp.async.wait_group 0;" ::: "memory")

// branch-free GELU: erf via A&S 7.1.26 (abs err < 1.5e-7)
__device__ __forceinline__ float gelu_erf(float x) {
    float u = 0.70710678118654752f * x;
    float a = fabsf(u);
    float den = fmaf(0.3275911f, a, 1.0f);
    float t;
    asm("rcp.approx.f32 %0, %1;" : "=f"(t) : "f"(den));
    float p = fmaf(fmaf(fmaf(fmaf(1.061405429f, t, -1.453152027f), t,
                             1.421413741f), t, -0.284496736f), t, 0.254829592f) * t;
    float e;
    asm("ex2.approx.f32 %0, %1;" : "=f"(e) : "f"(-a * a * 1.4426950408889634f));
    float erfa = fmaf(-p, e, 1.0f);
    float erfu = copysignf(erfa, u);
    return 0.5f * x * (1.0f + erfu);
}

// ---------------- prep: W1[0:512] -> fp16, [N,K] 48B-padded rows ------------
__global__ void prep_kernel(const float* __restrict__ W1) {
    int k = blockIdx.x;       // 0..511
    int n = threadIdx.x;      // 0..255
    __half h = __float2half_rn(W1[k * HN + n]);
    int c = k >> 4, kk = k & 15;
    char* base = (char*)&g_W1h[c][0];
    *(__half*)(base + n * RSB + kk * 2) = h;
}

// ---------------- A build: |xi - xj| exact fp16 hi/lo split -----------------
__device__ __forceinline__ void build_A(char* SB, uint32_t stg_off, int c, int tid) {
    int p  = tid >> 2;            // pair 0..63
    int k4 = (tid & 3) * 4;       // k offset 0,4,8,12
    const float* xi = (const float*)(SB + OFF_XI) + (p >> 4) * 512 + c * KC + k4;
    const float* xj = (const float*)(SB + OFF_XJ) + (p & 15) * 512 + c * KC + k4;
    float4 xa = *(const float4*)xi;
    float4 ya = *(const float4*)xj;
    float d0 = fabsf(xa.x - ya.x), d1 = fabsf(xa.y - ya.y);
    float d2 = fabsf(xa.z - ya.z), d3 = fabsf(xa.w - ya.w);
    __half2 h01 = __float22half2_rn(make_float2(d0, d1));
    __half2 h23 = __float22half2_rn(make_float2(d2, d3));
    __half2 l01 = __float22half2_rn(make_float2(d0 - __half2float(__low2half(h01)),
                                                d1 - __half2float(__high2half(h01))));
    __half2 l23 = __float22half2_rn(make_float2(d2 - __half2float(__low2half(h23)),
                                                d3 - __half2float(__high2half(h23))));
    uint32_t off = (uint32_t)(p * RSB + k4 * 2);
    *(uint2*)(SB + stg_off + ST_AH + off) = make_uint2(*(uint32_t*)&h01, *(uint32_t*)&h23);
    *(uint2*)(SB + stg_off + ST_AL + off) = make_uint2(*(uint32_t*)&l01, *(uint32_t*)&l23);
}

// ---------------- main scorer: 256 thr, tile M64 x N256, 2 CTAs/SM ----------
__global__ __launch_bounds__(256, 2)
void scorer_mma(const float* __restrict__ X,
                const float* __restrict__ logits,
                const float* __restrict__ b1,
                const float* __restrict__ W1,
                const float* __restrict__ W2,
                const float* __restrict__ b2,
                float* __restrict__ hs)
{
    const int ib = blockIdx.y;           // 0..255 (TI=4)
    const int jb = blockIdx.x;           // 0..63  (TJ=16)
    if (jb * TJ + (TJ - 1) < ib * TI) return;

    extern __shared__ __align__(128) char SB[];
    const uint32_t sb = smem_u32(SB);

    const int tid  = threadIdx.x;
    const int wid  = tid >> 5;
    const int lane = tid & 31;
    const int i0 = ib * TI, j0 = jb * TJ;

    // 8 warps: 2 M-groups x 4 N-groups; warp covers M32 x N64
    const int mg = wid >> 2, ng = wid & 3;
    const int m0 = mg * 32, n0 = ng * 64;

    // ---- preload X rows (fp32) + epilogue constants ----
    {
        float4* dXi = (float4*)(SB + OFF_XI);
        float4* dXj = (float4*)(SB + OFF_XJ);
#pragma unroll
        for (int r = 0; r < 2; r++) {
            int idx = tid + 256 * r;              // 512 float4
            dXi[idx] = ((const float4*)X)[(i0 + (idx >> 7)) * 128 + (idx & 127)];
        }
#pragma unroll
        for (int r = 0; r < 8; r++) {
            int idx = tid + 256 * r;              // 2048 float4
            dXj[idx] = ((const float4*)X)[(j0 + (idx >> 7)) * 128 + (idx & 127)];
        }
        float4* e = (float4*)(SB + OFF_EPI);
        e[tid] = make_float4(W1[512 * HN + tid], W1[513 * HN + tid],
                             b1[tid], W2[tid]);
    }
    __syncthreads();

    // ---- prologue: chunk 0 into stage 0 ----
    {
        const char* src = (const char*)&g_W1h[0][0];
        uint32_t dst = sb + OFF_ST + ST_B;
#pragma unroll
        for (int r = 0; r < 3; r++) {
            int idx = tid + 256 * r;              // 768 x 16B
            CP_ASYNC16(dst + idx * 16, src + idx * 16);
        }
        build_A(SB, OFF_ST, 0, tid);
        CP_COMMIT();
    }

    // ---- per-thread ldmatrix base offsets ----
    const uint32_t aBase = (uint32_t)((m0 + (lane & 7) + ((lane >> 3) & 1) * 8) * RSB
                                      + ((lane >> 4) & 1) * 16);
    const uint32_t bBase = (uint32_t)((n0 + (lane & 7) + ((lane >> 4) & 1) * 8) * RSB
                                      + ((lane >> 3) & 1) * 16);

    float d[2][4][2][4];
#pragma unroll
    for (int a = 0; a < 2; a++)
#pragma unroll
        for (int b = 0; b < 4; b++)
#pragma unroll
            for (int cc = 0; cc < 2; cc++)
#pragma unroll
                for (int r = 0; r < 4; r++) d[a][b][cc][r] = 0.0f;

    // ---- main K loop ----
    for (int c = 0; c < NCH; c++) {
        const int s = c & 1;
        CP_WAIT0();
        __syncthreads();

        if (c + 1 < NCH) {
            const char* src = (const char*)&g_W1h[c + 1][0];
            uint32_t dst = sb + OFF_ST + (s ^ 1) * STAGE_SZ + ST_B;
#pragma unroll
            for (int r = 0; r < 3; r++) {
                int idx = tid + 256 * r;
                CP_ASYNC16(dst + idx * 16, src + idx * 16);
            }
            build_A(SB, OFF_ST + (s ^ 1) * STAGE_SZ, c + 1, tid);
            CP_COMMIT();
        }

        const uint32_t stg = sb + OFF_ST + s * STAGE_SZ;
        uint32_t ahf[2][4], alf[2][4];
#pragma unroll
        for (int m2 = 0; m2 < 2; m2++) {
            uint32_t aa = stg + ST_AH + aBase + m2 * (16 * RSB);
            LDSM_X4(ahf[m2][0], ahf[m2][1], ahf[m2][2], ahf[m2][3], aa);
            LDSM_X4(alf[m2][0], alf[m2][1], alf[m2][2], alf[m2][3], aa + (ST_AL - ST_AH));
        }
#pragma unroll
        for (int nt = 0; nt < 4; nt++) {
            uint32_t ba = stg + ST_B + bBase + nt * (16 * RSB);
            uint32_t bh[4];
            LDSM_X4(bh[0], bh[1], bh[2], bh[3], ba);
#pragma unroll
            for (int m2 = 0; m2 < 2; m2++) {
                MMAH(d[m2][nt][0], ahf[m2][0],ahf[m2][1],ahf[m2][2],ahf[m2][3], bh[0], bh[1]);
                MMAH(d[m2][nt][0], alf[m2][0],alf[m2][1],alf[m2][2],alf[m2][3], bh[0], bh[1]);
                MMAH(d[m2][nt][1], ahf[m2][0],ahf[m2][1],ahf[m2][2],ahf[m2][3], bh[2], bh[3]);
                MMAH(d[m2][nt][1], alf[m2][0],alf[m2][1],alf[m2][2],alf[m2][3], bh[2], bh[3]);
            }
        }
    }
    __syncthreads();

    // ---- epilogue ----
    float c0[4], c1[4], sacc[4];
#pragma unroll
    for (int rr = 0; rr < 4; rr++) {
        int p = m0 + (lane >> 2) + 8 * rr;
        int gi = i0 + (p >> 4), gj = j0 + (p & 15);
        float pi = 1.0f / (1.0f + expf(logits[gi*2+1] - logits[gi*2]));
        float pj = 1.0f / (1.0f + expf(logits[gj*2+1] - logits[gj*2]));
        c0[rr] = pi * pj;
        c1[rr] = (1.0f - pi) * (1.0f - pj);
        sacc[rr] = 0.0f;
    }

    const float4* epi4 = (const float4*)(SB + OFF_EPI);
#pragma unroll
    for (int nt = 0; nt < 4; nt++)
#pragma unroll
        for (int half = 0; half < 2; half++)
#pragma unroll
            for (int e = 0; e < 2; e++) {
                int col = n0 + nt * 16 + half * 8 + (lane & 3) * 2 + e;
                float4 w = epi4[col];
#pragma unroll
                for (int rr = 0; rr < 4; rr++) {
                    int m2 = rr >> 1;
                    int idx = (rr & 1) * 2 + e;
                    float x = d[m2][nt][half][idx]
                            + c0[rr] * w.x + c1[rr] * w.y + w.z;
                    sacc[rr] = fmaf(gelu_erf(x), w.w, sacc[rr]);
                }
            }

#pragma unroll
    for (int rr = 0; rr < 4; rr++) {
        sacc[rr] += __shfl_xor_sync(0xffffffffu, sacc[rr], 1);
        sacc[rr] += __shfl_xor_sync(0xffffffffu, sacc[rr], 2);
    }
    float* red = (float*)(SB + OFF_RED);
    if ((lane & 3) == 0) {
#pragma unroll
        for (int rr = 0; rr < 4; rr++) {
            int p = m0 + (lane >> 2) + 8 * rr;
            red[p * 4 + ng] = sacc[rr];
        }
    }
    __syncthreads();

    if (tid < 64) {
        int p = tid;
        float4 r4 = *(const float4*)&red[p * 4];
        float tot = (r4.x + r4.y) + (r4.z + r4.w) + b2[0];
        float sc = 1.0f / (1.0f + expf(-tot));
        int gi = i0 + (p >> 4), gj = j0 + (p & 15);
        hs[gi * BN + gj] = sc;
        hs[gj * BN + gi] = sc;
    }
}

// ---------------- row softmax of adj + 5*log(hs + 1e-8) ----------------
__global__ __launch_bounds__(256)
void softmax_kernel(const float* __restrict__ adj,
                    const float* __restrict__ hs,
                    float* __restrict__ out)
{
    const int row = blockIdx.x;
    const int tid = threadIdx.x;
    __shared__ float red[256];

    float v[4];
    float mx = -3.4e38f;
#pragma unroll
    for (int u = 0; u < 4; u++) {
        int j = tid + 256 * u;
        float s = hs[row * BN + j];
        v[u] = adj[row * BN + j] + 5.0f * logf(s + 1e-8f);
        mx = fmaxf(mx, v[u]);
    }
    red[tid] = mx;
    __syncthreads();
    for (int off = 128; off > 0; off >>= 1) {
        if (tid < off) red[tid] = fmaxf(red[tid], red[tid + off]);
        __syncthreads();
    }
    mx = red[0];
    __syncthreads();

    float sum = 0.0f;
#pragma unroll
    for (int u = 0; u < 4; u++) {
        v[u] = expf(v[u] - mx);
        sum += v[u];
    }
    red[tid] = sum;
    __syncthreads();
    for (int off = 128; off > 0; off >>= 1) {
        if (tid < off) red[tid] += red[tid + off];
        __syncthreads();
    }
    float inv = 1.0f / red[0];
#pragma unroll
    for (int u = 0; u < 4; u++) {
        int j = tid + 256 * u;
        out[row * BN + j] = v[u] * inv;
    }
}

extern "C" void kernel_launch(void* const* d_in, const int* in_sizes, int n_in,
                              void* d_out, int out_size)
{
    const float* X      = (const float*)d_in[0];   // [1024, 512]
    const float* logits = (const float*)d_in[1];   // [1024, 2]
    const float* adj    = (const float*)d_in[2];   // [1024, 1024]
    const float* W1     = (const float*)d_in[3];   // [514, 256]
    const float* b1     = (const float*)d_in[4];   // [256]
    const float* W2     = (const float*)d_in[5];   // [256, 1]
    const float* b2     = (const float*)d_in[6];   // [1]

    float* out = (float*)d_out;          // [adj_refined (1M) | h_scores (1M)]
    float* hs  = out + BN * BN;

    static int configured = 0;
    if (!configured) {
        cudaFuncSetAttribute(scorer_mma, cudaFuncAttributeMaxDynamicSharedMemorySize, SMEM_TOTAL);
        configured = 1;
    }

    prep_kernel<<<FEATN, HN>>>(W1);
    dim3 grid(BN / TJ, BN / TI);   // (64, 256)
    scorer_mma<<<grid, 256, SMEM_TOTAL>>>(X, logits, b1, W1, W2, b2, hs);
    softmax_kernel<<<BN, 256>>>(adj, hs, out);
}

// round 8
// speedup vs baseline: 4.7039x; 1.2796x over previous
#include <cuda_runtime.h>
#include <cuda_fp16.h>
#include <math.h>
#include <stdint.h>

#define BN    1024
#define FEATN 512
#define HN    256
#define TI    4
#define TJ    16
#define KC    16       // k per chunk
#define NCH   32       // 512/16
#define RSB   48       // padded row stride bytes: conflict-free ldmatrix

// ---- smem layout (bytes from 128B-aligned dynamic base) ----
#define OFF_XI   0               // 4 x 512 f32  = 8192
#define OFF_XJ   8192            // 16 x 512 f32 = 32768
#define OFF_ST   40960           // 2 stages x 15360
#define STAGE_SZ 15360
#define ST_A     0               // A 64x48 = 3072
#define ST_B     3072            // B 256x48 = 12288
#define OFF_EPI  71680           // float4 per col: 256 x 16 = 4096
#define OFF_RED  75776           // 64 x 4 floats = 1024
#define SMEM_TOTAL 76800

// W1[0:512] rounded to fp16, transposed [N,K], 48B-padded rows: [chunk][768 uint4]
__device__ uint4 g_W1h[NCH][768];

__device__ __forceinline__ uint32_t smem_u32(const void* p) {
    uint32_t a;
    asm("{ .reg .u64 t; cvta.to.shared.u64 t, %1; cvt.u32.u64 %0, t; }" : "=r"(a) : "l"(p));
    return a;
}

#define LDSM_X4(r0,r1,r2,r3,addr) \
    asm volatile("ldmatrix.sync.aligned.m8n8.x4.shared.b16 {%0,%1,%2,%3}, [%4];" \
        : "=r"(r0), "=r"(r1), "=r"(r2), "=r"(r3) : "r"(addr))

#define MMAH(d, a0,a1,a2,a3, b0,b1) \
    asm volatile("mma.sync.aligned.m16n8k16.row.col.f32.f16.f16.f32 " \
        "{%0,%1,%2,%3}, {%4,%5,%6,%7}, {%8,%9}, {%0,%1,%2,%3};" \
        : "+f"((d)[0]), "+f"((d)[1]), "+f"((d)[2]), "+f"((d)[3]) \
        : "r"(a0), "r"(a1), "r"(a2), "r"(a3), "r"(b0), "r"(b1))

#define CP_ASYNC16(dst, src) \
    asm volatile("cp.async.cg.shared.global [%0], [%1], 16;" :: "r"(dst), "l"(src))
#define CP_COMMIT() asm volatile("cp.async.commit_group;" ::: "memory")
#define CP_WAIT0()  asm volatile("cp.async.wait_group 0;" ::: "memory")

// branch-free GELU: erf via A&S 7.1.26 (abs err < 1.5e-7)
__device__ __forceinline__ float gelu_erf(float x) {
    float u = 0.70710678118654752f * x;
    float a = fabsf(u);
    float den = fmaf(0.3275911f, a, 1.0f);
    float t;
    asm("rcp.approx.f32 %0, %1;" : "=f"(t) : "f"(den));
    float p = fmaf(fmaf(fmaf(fmaf(1.061405429f, t, -1.453152027f), t,
                             1.421413741f), t, -0.284496736f), t, 0.254829592f) * t;
    float e;
    asm("ex2.approx.f32 %0, %1;" : "=f"(e) : "f"(-a * a * 1.4426950408889634f));
    float erfa = fmaf(-p, e, 1.0f);
    float erfu = copysignf(erfa, u);
    return 0.5f * x * (1.0f + erfu);
}

// ---------------- prep: W1[0:512] -> fp16, [N,K] 48B-padded rows ------------
__global__ void prep_kernel(const float* __restrict__ W1) {
    int k = blockIdx.x;       // 0..511
    int n = threadIdx.x;      // 0..255
    __half h = __float2half_rn(W1[k * HN + n]);
    int c = k >> 4, kk = k & 15;
    char* base = (char*)&g_W1h[c][0];
    *(__half*)(base + n * RSB + kk * 2) = h;
}

// ---------------- A build: |xi - xj| -> fp16 --------------------------------
__device__ __forceinline__ void build_A(char* SB, uint32_t stg_off, int c, int tid) {
    int p  = tid >> 2;            // pair 0..63
    int k4 = (tid & 3) * 4;       // k offset 0,4,8,12
    const float* xi = (const float*)(SB + OFF_XI) + (p >> 4) * 512 + c * KC + k4;
    const float* xj = (const float*)(SB + OFF_XJ) + (p & 15) * 512 + c * KC + k4;
    float4 xa = *(const float4*)xi;
    float4 ya = *(const float4*)xj;
    __half2 h01 = __float22half2_rn(make_float2(fabsf(xa.x - ya.x), fabsf(xa.y - ya.y)));
    __half2 h23 = __float22half2_rn(make_float2(fabsf(xa.z - ya.z), fabsf(xa.w - ya.w)));
    uint32_t off = (uint32_t)(p * RSB + k4 * 2);
    *(uint2*)(SB + stg_off + ST_A + off) = make_uint2(*(uint32_t*)&h01, *(uint32_t*)&h23);
}

// ---------------- main scorer: 256 thr, tile M64 x N256, 2 CTAs/SM ----------
__global__ __launch_bounds__(256, 2)
void scorer_mma(const float* __restrict__ X,
                const float* __restrict__ logits,
                const float* __restrict__ b1,
                const float* __restrict__ W1,
                const float* __restrict__ W2,
                const float* __restrict__ b2,
                float* __restrict__ hs)
{
    const int ib = blockIdx.y;           // 0..255 (TI=4)
    const int jb = blockIdx.x;           // 0..63  (TJ=16)
    if (jb * TJ + (TJ - 1) < ib * TI) return;

    extern __shared__ __align__(128) char SB[];
    const uint32_t sb = smem_u32(SB);

    const int tid  = threadIdx.x;
    const int wid  = tid >> 5;
    const int lane = tid & 31;
    const int i0 = ib * TI, j0 = jb * TJ;

    // 8 warps: 2 M-groups x 4 N-groups; warp covers M32 x N64
    const int mg = wid >> 2, ng = wid & 3;
    const int m0 = mg * 32, n0 = ng * 64;

    // ---- preload X rows (fp32) + epilogue constants ----
    {
        float4* dXi = (float4*)(SB + OFF_XI);
        float4* dXj = (float4*)(SB + OFF_XJ);
#pragma unroll
        for (int r = 0; r < 2; r++) {
            int idx = tid + 256 * r;              // 512 float4
            dXi[idx] = ((const float4*)X)[(i0 + (idx >> 7)) * 128 + (idx & 127)];
        }
#pragma unroll
        for (int r = 0; r < 8; r++) {
            int idx = tid + 256 * r;              // 2048 float4
            dXj[idx] = ((const float4*)X)[(j0 + (idx >> 7)) * 128 + (idx & 127)];
        }
        float4* e = (float4*)(SB + OFF_EPI);
        e[tid] = make_float4(W1[512 * HN + tid], W1[513 * HN + tid],
                             b1[tid], W2[tid]);
    }
    __syncthreads();

    // ---- prologue: chunk 0 into stage 0 ----
    {
        const char* src = (const char*)&g_W1h[0][0];
        uint32_t dst = sb + OFF_ST + ST_B;
#pragma unroll
        for (int r = 0; r < 3; r++) {
            int idx = tid + 256 * r;              // 768 x 16B
            CP_ASYNC16(dst + idx * 16, src + idx * 16);
        }
        build_A(SB, OFF_ST, 0, tid);
        CP_COMMIT();
    }

    // ---- per-thread ldmatrix base offsets ----
    const uint32_t aBase = (uint32_t)((m0 + (lane & 7) + ((lane >> 3) & 1) * 8) * RSB
                                      + ((lane >> 4) & 1) * 16);
    const uint32_t bBase = (uint32_t)((n0 + (lane & 7) + ((lane >> 4) & 1) * 8) * RSB
                                      + ((lane >> 3) & 1) * 16);

    float d[2][4][2][4];
#pragma unroll
    for (int a = 0; a < 2; a++)
#pragma unroll
        for (int b = 0; b < 4; b++)
#pragma unroll
            for (int cc = 0; cc < 2; cc++)
#pragma unroll
                for (int r = 0; r < 4; r++) d[a][b][cc][r] = 0.0f;

    // ---- main K loop ----
    for (int c = 0; c < NCH; c++) {
        const int s = c & 1;
        CP_WAIT0();
        __syncthreads();

        if (c + 1 < NCH) {
            const char* src = (const char*)&g_W1h[c + 1][0];
            uint32_t dst = sb + OFF_ST + (s ^ 1) * STAGE_SZ + ST_B;
#pragma unroll
            for (int r = 0; r < 3; r++) {
                int idx = tid + 256 * r;
                CP_ASYNC16(dst + idx * 16, src + idx * 16);
            }
            build_A(SB, OFF_ST + (s ^ 1) * STAGE_SZ, c + 1, tid);
            CP_COMMIT();
        }

        const uint32_t stg = sb + OFF_ST + s * STAGE_SZ;
        uint32_t af[2][4];
#pragma unroll
        for (int m2 = 0; m2 < 2; m2++) {
            uint32_t aa = stg + ST_A + aBase + m2 * (16 * RSB);
            LDSM_X4(af[m2][0], af[m2][1], af[m2][2], af[m2][3], aa);
        }
#pragma unroll
        for (int nt = 0; nt < 4; nt++) {
            uint32_t ba = stg + ST_B + bBase + nt * (16 * RSB);
            uint32_t bh[4];
            LDSM_X4(bh[0], bh[1], bh[2], bh[3], ba);
#pragma unroll
            for (int m2 = 0; m2 < 2; m2++) {
                MMAH(d[m2][nt][0], af[m2][0],af[m2][1],af[m2][2],af[m2][3], bh[0], bh[1]);
                MMAH(d[m2][nt][1], af[m2][0],af[m2][1],af[m2][2],af[m2][3], bh[2], bh[3]);
            }
        }
    }
    __syncthreads();

    // ---- epilogue ----
    float c0[4], c1[4], sacc[4];
#pragma unroll
    for (int rr = 0; rr < 4; rr++) {
        int p = m0 + (lane >> 2) + 8 * rr;
        int gi = i0 + (p >> 4), gj = j0 + (p & 15);
        float pi = 1.0f / (1.0f + expf(logits[gi*2+1] - logits[gi*2]));
        float pj = 1.0f / (1.0f + expf(logits[gj*2+1] - logits[gj*2]));
        c0[rr] = pi * pj;
        c1[rr] = (1.0f - pi) * (1.0f - pj);
        sacc[rr] = 0.0f;
    }

    const float4* epi4 = (const float4*)(SB + OFF_EPI);
#pragma unroll
    for (int nt = 0; nt < 4; nt++)
#pragma unroll
        for (int half = 0; half < 2; half++)
#pragma unroll
            for (int e = 0; e < 2; e++) {
                int col = n0 + nt * 16 + half * 8 + (lane & 3) * 2 + e;
                float4 w = epi4[col];
#pragma unroll
                for (int rr = 0; rr < 4; rr++) {
                    int m2 = rr >> 1;
                    int idx = (rr & 1) * 2 + e;
                    float x = d[m2][nt][half][idx]
                            + c0[rr] * w.x + c1[rr] * w.y + w.z;
                    sacc[rr] = fmaf(gelu_erf(x), w.w, sacc[rr]);
                }
            }

#pragma unroll
    for (int rr = 0; rr < 4; rr++) {
        sacc[rr] += __shfl_xor_sync(0xffffffffu, sacc[rr], 1);
        sacc[rr] += __shfl_xor_sync(0xffffffffu, sacc[rr], 2);
    }
    float* red = (float*)(SB + OFF_RED);
    if ((lane & 3) == 0) {
#pragma unroll
        for (int rr = 0; rr < 4; rr++) {
            int p = m0 + (lane >> 2) + 8 * rr;
            red[p * 4 + ng] = sacc[rr];
        }
    }
    __syncthreads();

    if (tid < 64) {
        int p = tid;
        float4 r4 = *(const float4*)&red[p * 4];
        float tot = (r4.x + r4.y) + (r4.z + r4.w) + b2[0];
        float sc = 1.0f / (1.0f + expf(-tot));
        int gi = i0 + (p >> 4), gj = j0 + (p & 15);
        hs[gi * BN + gj] = sc;
        hs[gj * BN + gi] = sc;
    }
}

// ---------------- row softmax of adj + 5*log(hs + 1e-8) ----------------
__global__ __launch_bounds__(256)
void softmax_kernel(const float* __restrict__ adj,
                    const float* __restrict__ hs,
                    float* __restrict__ out)
{
    const int row = blockIdx.x;
    const int tid = threadIdx.x;
    __shared__ float red[256];

    float v[4];
    float mx = -3.4e38f;
#pragma unroll
    for (int u = 0; u < 4; u++) {
        int j = tid + 256 * u;
        float s = hs[row * BN + j];
        v[u] = adj[row * BN + j] + 5.0f * logf(s + 1e-8f);
        mx = fmaxf(mx, v[u]);
    }
    red[tid] = mx;
    __syncthreads();
    for (int off = 128; off > 0; off >>= 1) {
        if (tid < off) red[tid] = fmaxf(red[tid], red[tid + off]);
        __syncthreads();
    }
    mx = red[0];
    __syncthreads();

    float sum = 0.0f;
#pragma unroll
    for (int u = 0; u < 4; u++) {
        v[u] = expf(v[u] - mx);
        sum += v[u];
    }
    red[tid] = sum;
    __syncthreads();
    for (int off = 128; off > 0; off >>= 1) {
        if (tid < off) red[tid] += red[tid + off];
        __syncthreads();
    }
    float inv = 1.0f / red[0];
#pragma unroll
    for (int u = 0; u < 4; u++) {
        int j = tid + 256 * u;
        out[row * BN + j] = v[u] * inv;
    }
}

extern "C" void kernel_launch(void* const* d_in, const int* in_sizes, int n_in,
                              void* d_out, int out_size)
{
    const float* X      = (const float*)d_in[0];   // [1024, 512]
    const float* logits = (const float*)d_in[1];   // [1024, 2]
    const float* adj    = (const float*)d_in[2];   // [1024, 1024]
    const float* W1     = (const float*)d_in[3];   // [514, 256]
    const float* b1     = (const float*)d_in[4];   // [256]
    const float* W2     = (const float*)d_in[5];   // [256, 1]
    const float* b2     = (const float*)d_in[6];   // [1]

    float* out = (float*)d_out;          // [adj_refined (1M) | h_scores (1M)]
    float* hs  = out + BN * BN;

    static int configured = 0;
    if (!configured) {
        cudaFuncSetAttribute(scorer_mma, cudaFuncAttributeMaxDynamicSharedMemorySize, SMEM_TOTAL);
        configured = 1;
    }

    prep_kernel<<<FEATN, HN>>>(W1);
    dim3 grid(BN / TJ, BN / TI);   // (64, 256)
    scorer_mma<<<grid, 256, SMEM_TOTAL>>>(X, logits, b1, W1, W2, b2, hs);
    softmax_kernel<<<BN, 256>>>(adj, hs, out);
}

// round 9
// speedup vs baseline: 5.2713x; 1.1206x over previous
#include <cuda_runtime.h>
#include <cuda_fp16.h>
#include <math.h>
#include <stdint.h>

#define BN    1024
#define FEATN 512
#define HN    256
#define TI    4
#define TJ    16
#define KC    16       // k per chunk
#define NCH   32       // 512/16
#define RSB   48       // padded A row stride bytes: conflict-free ldmatrix

// ---- smem layout (bytes from 128B-aligned dynamic base) ----
#define OFF_XI   0               // 4 x 512 f32  = 8192
#define OFF_XJ   8192            // 16 x 512 f32 = 32768
#define OFF_ST   40960           // 2 A stages x 3072
#define STAGE_SZ 3072
#define OFF_EPI  47104           // float4 per col: 256 x 16 = 4096
#define OFF_RED  51200           // 64 x 4 floats = 1024
#define SMEM_TOTAL 52224

// W1[0:512] as fp16 MMA B-fragments, per-lane order:
// index = c*512 + (ng*4+nt)*32 + lane ; 16B = {tile 2t: b0,b1 | tile 2t+1: b0,b1}
__device__ uint4 g_Bf[NCH * 512];

__device__ __forceinline__ uint32_t smem_u32(const void* p) {
    uint32_t a;
    asm("{ .reg .u64 t; cvta.to.shared.u64 t, %1; cvt.u32.u64 %0, t; }" : "=r"(a) : "l"(p));
    return a;
}

#define LDSM_X4(r0,r1,r2,r3,addr) \
    asm volatile("ldmatrix.sync.aligned.m8n8.x4.shared.b16 {%0,%1,%2,%3}, [%4];" \
        : "=r"(r0), "=r"(r1), "=r"(r2), "=r"(r3) : "r"(addr))

#define MMAH(d, a0,a1,a2,a3, b0,b1) \
    asm volatile("mma.sync.aligned.m16n8k16.row.col.f32.f16.f16.f32 " \
        "{%0,%1,%2,%3}, {%4,%5,%6,%7}, {%8,%9}, {%0,%1,%2,%3};" \
        : "+f"((d)[0]), "+f"((d)[1]), "+f"((d)[2]), "+f"((d)[3]) \
        : "r"(a0), "r"(a1), "r"(a2), "r"(a3), "r"(b0), "r"(b1))

// branch-free GELU: erf via A&S 7.1.26 (abs err < 1.5e-7)
__device__ __forceinline__ float gelu_erf(float x) {
    float u = 0.70710678118654752f * x;
    float a = fabsf(u);
    float den = fmaf(0.3275911f, a, 1.0f);
    float t;
    asm("rcp.approx.f32 %0, %1;" : "=f"(t) : "f"(den));
    float p = fmaf(fmaf(fmaf(fmaf(1.061405429f, t, -1.453152027f), t,
                             1.421413741f), t, -0.284496736f), t, 0.254829592f) * t;
    float e;
    asm("ex2.approx.f32 %0, %1;" : "=f"(e) : "f"(-a * a * 1.4426950408889634f));
    float erfa = fmaf(-p, e, 1.0f);
    float erfu = copysignf(erfa, u);
    return 0.5f * x * (1.0f + erfu);
}

// ---- prep: W1[0:512] -> fp16 B fragments in per-lane MMA order -------------
// thread idx = c*512 + tp*32 + lane ; tiles t = 2tp, 2tp+1 ; n = t*8 + lane/4
// b0 = {B[k][n], B[k+1][n]}, b1 = {B[k+8][n], B[k+9][n]}, k = c*16 + (lane%4)*2
__global__ void prep_frag(const float* __restrict__ W1) {
    int idx  = blockIdx.x * 256 + threadIdx.x;    // 0..16383
    int lane = idx & 31;
    int tp   = (idx >> 5) & 15;
    int c    = idx >> 9;
    int kg   = c * 16 + (lane & 3) * 2;
    uint32_t e[4];
#pragma unroll
    for (int t2 = 0; t2 < 2; t2++) {
        int n = (tp * 2 + t2) * 8 + (lane >> 2);
        __half2 b0 = __floats2half2_rn(W1[kg * HN + n],       W1[(kg + 1) * HN + n]);
        __half2 b1 = __floats2half2_rn(W1[(kg + 8) * HN + n], W1[(kg + 9) * HN + n]);
        e[t2 * 2]     = *(uint32_t*)&b0;
        e[t2 * 2 + 1] = *(uint32_t*)&b1;
    }
    g_Bf[idx] = make_uint4(e[0], e[1], e[2], e[3]);
}

// ---- A build: |xi - xj| -> fp16 into stage ---------------------------------
__device__ __forceinline__ void build_A(char* SB, uint32_t stg_off, int c, int tid) {
    int p  = tid >> 2;            // pair 0..63
    int k4 = (tid & 3) * 4;       // k offset 0,4,8,12
    const float* xi = (const float*)(SB + OFF_XI) + (p >> 4) * 512 + c * KC + k4;
    const float* xj = (const float*)(SB + OFF_XJ) + (p & 15) * 512 + c * KC + k4;
    float4 xa = *(const float4*)xi;
    float4 ya = *(const float4*)xj;
    __half2 h01 = __float22half2_rn(make_float2(fabsf(xa.x - ya.x), fabsf(xa.y - ya.y)));
    __half2 h23 = __float22half2_rn(make_float2(fabsf(xa.z - ya.z), fabsf(xa.w - ya.w)));
    uint32_t off = (uint32_t)(p * RSB + k4 * 2);
    *(uint2*)(SB + stg_off + off) = make_uint2(*(uint32_t*)&h01, *(uint32_t*)&h23);
}

// ---- main scorer: 256 thr, tile M64 x N256, 2 CTAs/SM ----------------------
__global__ __launch_bounds__(256, 2)
void scorer_mma(const float* __restrict__ X,
                const float* __restrict__ logits,
                const float* __restrict__ b1,
                const float* __restrict__ W1,
                const float* __restrict__ W2,
                const float* __restrict__ b2,
                float* __restrict__ hs)
{
    const int ib = blockIdx.y;           // 0..255 (TI=4)
    const int jb = blockIdx.x;           // 0..63  (TJ=16)
    if (jb * TJ + (TJ - 1) < ib * TI) return;

    extern __shared__ __align__(128) char SB[];
    const uint32_t sb = smem_u32(SB);

    const int tid  = threadIdx.x;
    const int wid  = tid >> 5;
    const int lane = tid & 31;
    const int i0 = ib * TI, j0 = jb * TJ;

    // 8 warps: 2 M-groups x 4 N-groups; warp covers M32 x N64
    const int mg = wid >> 2, ng = wid & 3;
    const int m0 = mg * 32, n0 = ng * 64;

    // ---- preload X rows (fp32) + epilogue constants ----
    {
        float4* dXi = (float4*)(SB + OFF_XI);
        float4* dXj = (float4*)(SB + OFF_XJ);
#pragma unroll
        for (int r = 0; r < 2; r++) {
            int idx = tid + 256 * r;              // 512 float4
            dXi[idx] = ((const float4*)X)[(i0 + (idx >> 7)) * 128 + (idx & 127)];
        }
#pragma unroll
        for (int r = 0; r < 8; r++) {
            int idx = tid + 256 * r;              // 2048 float4
            dXj[idx] = ((const float4*)X)[(j0 + (idx >> 7)) * 128 + (idx & 127)];
        }
        float4* e = (float4*)(SB + OFF_EPI);
        e[tid] = make_float4(W1[512 * HN + tid], W1[513 * HN + tid],
                             b1[tid], W2[tid]);
    }
    __syncthreads();

    build_A(SB, OFF_ST, 0, tid);
    __syncthreads();

    // ---- per-thread A ldmatrix base offset ----
    const uint32_t aBase = (uint32_t)((m0 + (lane & 7) + ((lane >> 3) & 1) * 8) * RSB
                                      + ((lane >> 4) & 1) * 16);
    const uint4* __restrict__ gB = &g_Bf[ng * 128 + lane];

    float d[2][4][2][4];
#pragma unroll
    for (int a = 0; a < 2; a++)
#pragma unroll
        for (int b = 0; b < 4; b++)
#pragma unroll
            for (int cc = 0; cc < 2; cc++)
#pragma unroll
                for (int r = 0; r < 4; r++) d[a][b][cc][r] = 0.0f;

    // ---- main K loop ----
    for (int c = 0; c < NCH; c++) {
        const int s = c & 1;
        const uint32_t stg = sb + OFF_ST + s * STAGE_SZ;

        // B fragments straight from global (L1/L2 resident, coalesced 512B/warp)
        uint4 Bv[4];
#pragma unroll
        for (int nt = 0; nt < 4; nt++)
            Bv[nt] = __ldg(gB + c * 512 + nt * 32);

        uint32_t af[2][4];
#pragma unroll
        for (int m2 = 0; m2 < 2; m2++) {
            uint32_t aa = stg + aBase + m2 * (16 * RSB);
            LDSM_X4(af[m2][0], af[m2][1], af[m2][2], af[m2][3], aa);
        }

        if (c + 1 < NCH)
            build_A(SB, OFF_ST + (s ^ 1) * STAGE_SZ, c + 1, tid);

#pragma unroll
        for (int nt = 0; nt < 4; nt++)
#pragma unroll
            for (int m2 = 0; m2 < 2; m2++) {
                MMAH(d[m2][nt][0], af[m2][0],af[m2][1],af[m2][2],af[m2][3], Bv[nt].x, Bv[nt].y);
                MMAH(d[m2][nt][1], af[m2][0],af[m2][1],af[m2][2],af[m2][3], Bv[nt].z, Bv[nt].w);
            }
        __syncthreads();
    }

    // ---- epilogue ----
    float c0[4], c1[4], sacc[4];
#pragma unroll
    for (int rr = 0; rr < 4; rr++) {
        int p = m0 + (lane >> 2) + 8 * rr;
        int gi = i0 + (p >> 4), gj = j0 + (p & 15);
        float pi = 1.0f / (1.0f + expf(logits[gi*2+1] - logits[gi*2]));
        float pj = 1.0f / (1.0f + expf(logits[gj*2+1] - logits[gj*2]));
        c0[rr] = pi * pj;
        c1[rr] = (1.0f - pi) * (1.0f - pj);
        sacc[rr] = 0.0f;
    }

    const float4* epi4 = (const float4*)(SB + OFF_EPI);
#pragma unroll
    for (int nt = 0; nt < 4; nt++)
#pragma unroll
        for (int half = 0; half < 2; half++)
#pragma unroll
            for (int e = 0; e < 2; e++) {
                int col = n0 + nt * 16 + half * 8 + (lane & 3) * 2 + e;
                float4 w = epi4[col];
#pragma unroll
                for (int rr = 0; rr < 4; rr++) {
                    int m2 = rr >> 1;
                    int idx = (rr & 1) * 2 + e;
                    float x = d[m2][nt][half][idx]
                            + c0[rr] * w.x + c1[rr] * w.y + w.z;
                    sacc[rr] = fmaf(gelu_erf(x), w.w, sacc[rr]);
                }
            }

#pragma unroll
    for (int rr = 0; rr < 4; rr++) {
        sacc[rr] += __shfl_xor_sync(0xffffffffu, sacc[rr], 1);
        sacc[rr] += __shfl_xor_sync(0xffffffffu, sacc[rr], 2);
    }
    float* red = (float*)(SB + OFF_RED);
    if ((lane & 3) == 0) {
#pragma unroll
        for (int rr = 0; rr < 4; rr++) {
            int p = m0 + (lane >> 2) + 8 * rr;
            red[p * 4 + ng] = sacc[rr];
        }
    }
    __syncthreads();

    if (tid < 64) {
        int p = tid;
        float4 r4 = *(const float4*)&red[p * 4];
        float tot = (r4.x + r4.y) + (r4.z + r4.w) + b2[0];
        float sc = 1.0f / (1.0f + expf(-tot));
        int gi = i0 + (p >> 4), gj = j0 + (p & 15);
        hs[gi * BN + gj] = sc;
        hs[gj * BN + gi] = sc;
    }
}

// ---------------- row softmax of adj + 5*log(hs + 1e-8) ----------------
__global__ __launch_bounds__(256)
void softmax_kernel(const float* __restrict__ adj,
                    const float* __restrict__ hs,
                    float* __restrict__ out)
{
    const int row = blockIdx.x;
    const int tid = threadIdx.x;
    __shared__ float red[256];

    float v[4];
    float mx = -3.4e38f;
#pragma unroll
    for (int u = 0; u < 4; u++) {
        int j = tid + 256 * u;
        float s = hs[row * BN + j];
        v[u] = adj[row * BN + j] + 5.0f * logf(s + 1e-8f);
        mx = fmaxf(mx, v[u]);
    }
    red[tid] = mx;
    __syncthreads();
    for (int off = 128; off > 0; off >>= 1) {
        if (tid < off) red[tid] = fmaxf(red[tid], red[tid + off]);
        __syncthreads();
    }
    mx = red[0];
    __syncthreads();

    float sum = 0.0f;
#pragma unroll
    for (int u = 0; u < 4; u++) {
        v[u] = expf(v[u] - mx);
        sum += v[u];
    }
    red[tid] = sum;
    __syncthreads();
    for (int off = 128; off > 0; off >>= 1) {
        if (tid < off) red[tid] += red[tid + off];
        __syncthreads();
    }
    float inv = 1.0f / red[0];
#pragma unroll
    for (int u = 0; u < 4; u++) {
        int j = tid + 256 * u;
        out[row * BN + j] = v[u] * inv;
    }
}

extern "C" void kernel_launch(void* const* d_in, const int* in_sizes, int n_in,
                              void* d_out, int out_size)
{
    const float* X      = (const float*)d_in[0];   // [1024, 512]
    const float* logits = (const float*)d_in[1];   // [1024, 2]
    const float* adj    = (const float*)d_in[2];   // [1024, 1024]
    const float* W1     = (const float*)d_in[3];   // [514, 256]
    const float* b1     = (const float*)d_in[4];   // [256]
    const float* W2     = (const float*)d_in[5];   // [256, 1]
    const float* b2     = (const float*)d_in[6];   // [1]

    float* out = (float*)d_out;          // [adj_refined (1M) | h_scores (1M)]
    float* hs  = out + BN * BN;

    static int configured = 0;
    if (!configured) {
        cudaFuncSetAttribute(scorer_mma, cudaFuncAttributeMaxDynamicSharedMemorySize, SMEM_TOTAL);
        configured = 1;
    }

    prep_frag<<<64, 256>>>(W1);
    dim3 grid(BN / TJ, BN / TI);   // (64, 256)
    scorer_mma<<<grid, 256, SMEM_TOTAL>>>(X, logits, b1, W1, W2, b2, hs);
    softmax_kernel<<<BN, 256>>>(adj, hs, out);
}

// round 10
// speedup vs baseline: 5.5956x; 1.0615x over previous
#include <cuda_runtime.h>
#include <cuda_fp16.h>
#include <math.h>
#include <stdint.h>

#define BN    1024
#define FEATN 512
#define HN    256
#define TI    4
#define TJ    16
#define KC    32       // k per chunk (2 k16 slabs)
#define NCH   16       // 512/32
#define RSB   80       // padded A row stride bytes: conflict-free ldmatrix

// ---- smem layout (bytes from 128B-aligned dynamic base) ----
#define OFF_XI   0               // 4 x 512 f32  = 8192
#define OFF_XJ   8192            // 16 x 512 f32 = 32768
#define OFF_ST   40960           // 2 A stages x 5120
#define STAGE_SZ 5120
#define OFF_EPI  51200           // float4 per col: 256 x 16 = 4096
#define OFF_RED  55296           // 64 x 4 floats = 1024
#define SMEM_TOTAL 56320

// W1[0:512] as fp16 MMA B-fragments, per-lane order (indexed by k16 slab 0..31):
// index = cc*512 + (ng*4+nt)*32 + lane ; 16B = {tile 2t: b0,b1 | tile 2t+1: b0,b1}
__device__ uint4 g_Bf[32 * 512];

__device__ __forceinline__ uint32_t smem_u32(const void* p) {
    uint32_t a;
    asm("{ .reg .u64 t; cvta.to.shared.u64 t, %1; cvt.u32.u64 %0, t; }" : "=r"(a) : "l"(p));
    return a;
}

#define LDSM_X4(r0,r1,r2,r3,addr) \
    asm volatile("ldmatrix.sync.aligned.m8n8.x4.shared.b16 {%0,%1,%2,%3}, [%4];" \
        : "=r"(r0), "=r"(r1), "=r"(r2), "=r"(r3) : "r"(addr))

#define MMAH(d, a0,a1,a2,a3, b0,b1) \
    asm volatile("mma.sync.aligned.m16n8k16.row.col.f32.f16.f16.f32 " \
        "{%0,%1,%2,%3}, {%4,%5,%6,%7}, {%8,%9}, {%0,%1,%2,%3};" \
        : "+f"((d)[0]), "+f"((d)[1]), "+f"((d)[2]), "+f"((d)[3]) \
        : "r"(a0), "r"(a1), "r"(a2), "r"(a3), "r"(b0), "r"(b1))

// branch-free GELU: erf via A&S 7.1.26 (abs err < 1.5e-7)
__device__ __forceinline__ float gelu_erf(float x) {
    float u = 0.70710678118654752f * x;
    float a = fabsf(u);
    float den = fmaf(0.3275911f, a, 1.0f);
    float t;
    asm("rcp.approx.f32 %0, %1;" : "=f"(t) : "f"(den));
    float p = fmaf(fmaf(fmaf(fmaf(1.061405429f, t, -1.453152027f), t,
                             1.421413741f), t, -0.284496736f), t, 0.254829592f) * t;
    float e;
    asm("ex2.approx.f32 %0, %1;" : "=f"(e) : "f"(-a * a * 1.4426950408889634f));
    float erfa = fmaf(-p, e, 1.0f);
    float erfu = copysignf(erfa, u);
    return 0.5f * x * (1.0f + erfu);
}

// ---- prep: W1[0:512] -> fp16 B fragments in per-lane MMA order -------------
__global__ void prep_frag(const float* __restrict__ W1) {
    int idx  = blockIdx.x * 256 + threadIdx.x;    // 0..16383
    int lane = idx & 31;
    int tp   = (idx >> 5) & 15;
    int cc   = idx >> 9;                          // k16 slab 0..31
    int kg   = cc * 16 + (lane & 3) * 2;
    uint32_t e[4];
#pragma unroll
    for (int t2 = 0; t2 < 2; t2++) {
        int n = (tp * 2 + t2) * 8 + (lane >> 2);
        __half2 b0 = __floats2half2_rn(W1[kg * HN + n],       W1[(kg + 1) * HN + n]);
        __half2 b1 = __floats2half2_rn(W1[(kg + 8) * HN + n], W1[(kg + 9) * HN + n]);
        e[t2 * 2]     = *(uint32_t*)&b0;
        e[t2 * 2 + 1] = *(uint32_t*)&b1;
    }
    g_Bf[idx] = make_uint4(e[0], e[1], e[2], e[3]);
}

// ---- A build: |xi - xj| -> fp16, 8 k per thread, chunk of 32 k -------------
__device__ __forceinline__ void build_A(char* SB, uint32_t stg_off, int c, int tid) {
    int p  = tid >> 2;            // pair 0..63
    int kq = (tid & 3) * 8;       // k offset 0,8,16,24
    const float* xi = (const float*)(SB + OFF_XI) + (p >> 4) * 512 + c * KC + kq;
    const float* xj = (const float*)(SB + OFF_XJ) + (p & 15) * 512 + c * KC + kq;
    float4 xa = *(const float4*)xi, xb = *(const float4*)(xi + 4);
    float4 ya = *(const float4*)xj, yb = *(const float4*)(xj + 4);
    __half2 h0 = __float22half2_rn(make_float2(fabsf(xa.x - ya.x), fabsf(xa.y - ya.y)));
    __half2 h1 = __float22half2_rn(make_float2(fabsf(xa.z - ya.z), fabsf(xa.w - ya.w)));
    __half2 h2 = __float22half2_rn(make_float2(fabsf(xb.x - yb.x), fabsf(xb.y - yb.y)));
    __half2 h3 = __float22half2_rn(make_float2(fabsf(xb.z - yb.z), fabsf(xb.w - yb.w)));
    uint32_t off = (uint32_t)(p * RSB + kq * 2);
    *(uint4*)(SB + stg_off + off) = make_uint4(*(uint32_t*)&h0, *(uint32_t*)&h1,
                                               *(uint32_t*)&h2, *(uint32_t*)&h3);
}

// ---- main scorer: 256 thr, tile M64 x N256, 2 CTAs/SM ----------------------
__global__ __launch_bounds__(256, 2)
void scorer_mma(const float* __restrict__ X,
                const float* __restrict__ logits,
                const float* __restrict__ b1,
                const float* __restrict__ W1,
                const float* __restrict__ W2,
                const float* __restrict__ b2,
                float* __restrict__ hs)
{
    const int ib = blockIdx.y;           // 0..255 (TI=4)
    const int jb = blockIdx.x;           // 0..63  (TJ=16)
    if (jb * TJ + (TJ - 1) < ib * TI) return;

    extern __shared__ __align__(128) char SB[];
    const uint32_t sb = smem_u32(SB);

    const int tid  = threadIdx.x;
    const int wid  = tid >> 5;
    const int lane = tid & 31;
    const int i0 = ib * TI, j0 = jb * TJ;

    // 8 warps: 2 M-groups x 4 N-groups; warp covers M32 x N64
    const int mg = wid >> 2, ng = wid & 3;
    const int m0 = mg * 32, n0 = ng * 64;

    // ---- preload X rows (fp32) + epilogue constants ----
    {
        float4* dXi = (float4*)(SB + OFF_XI);
        float4* dXj = (float4*)(SB + OFF_XJ);
#pragma unroll
        for (int r = 0; r < 2; r++) {
            int idx = tid + 256 * r;              // 512 float4
            dXi[idx] = ((const float4*)X)[(i0 + (idx >> 7)) * 128 + (idx & 127)];
        }
#pragma unroll
        for (int r = 0; r < 8; r++) {
            int idx = tid + 256 * r;              // 2048 float4
            dXj[idx] = ((const float4*)X)[(j0 + (idx >> 7)) * 128 + (idx & 127)];
        }
        float4* e = (float4*)(SB + OFF_EPI);
        e[tid] = make_float4(W1[512 * HN + tid], W1[513 * HN + tid],
                             b1[tid], W2[tid]);
    }
    __syncthreads();

    build_A(SB, OFF_ST, 0, tid);

    // ---- per-thread A ldmatrix base offset ----
    const uint32_t aBase = (uint32_t)((m0 + (lane & 7) + ((lane >> 3) & 1) * 8) * RSB
                                      + ((lane >> 4) & 1) * 16);
    const uint4* __restrict__ gB = &g_Bf[ng * 128 + lane];

    float d[2][4][2][4];
#pragma unroll
    for (int a = 0; a < 2; a++)
#pragma unroll
        for (int b = 0; b < 4; b++)
#pragma unroll
            for (int cc = 0; cc < 2; cc++)
#pragma unroll
                for (int r = 0; r < 4; r++) d[a][b][cc][r] = 0.0f;

    // ---- main K loop: 16 chunks of k32 ----
    for (int c = 0; c < NCH; c++) {
        const int s = c & 1;
        __syncthreads();
        const uint32_t stg = sb + OFF_ST + s * STAGE_SZ;

        // B fragments for both k16 slabs, straight from global (hot in L1/L2)
        uint4 Bv[8];
#pragma unroll
        for (int ks = 0; ks < 2; ks++)
#pragma unroll
            for (int nt = 0; nt < 4; nt++)
                Bv[ks * 4 + nt] = __ldg(gB + (c * 2 + ks) * 512 + nt * 32);

        uint32_t af[2][2][4];
#pragma unroll
        for (int ks = 0; ks < 2; ks++)
#pragma unroll
            for (int m2 = 0; m2 < 2; m2++) {
                uint32_t aa = stg + aBase + m2 * (16 * RSB) + ks * 32;
                LDSM_X4(af[ks][m2][0], af[ks][m2][1], af[ks][m2][2], af[ks][m2][3], aa);
            }

        if (c + 1 < NCH)
            build_A(SB, OFF_ST + (s ^ 1) * STAGE_SZ, c + 1, tid);

#pragma unroll
        for (int ks = 0; ks < 2; ks++)
#pragma unroll
            for (int nt = 0; nt < 4; nt++)
#pragma unroll
                for (int m2 = 0; m2 < 2; m2++) {
                    MMAH(d[m2][nt][0], af[ks][m2][0],af[ks][m2][1],af[ks][m2][2],af[ks][m2][3],
                         Bv[ks*4+nt].x, Bv[ks*4+nt].y);
                    MMAH(d[m2][nt][1], af[ks][m2][0],af[ks][m2][1],af[ks][m2][2],af[ks][m2][3],
                         Bv[ks*4+nt].z, Bv[ks*4+nt].w);
                }
    }
    __syncthreads();

    // ---- epilogue ----
    float c0[4], c1[4], sacc[4];
#pragma unroll
    for (int rr = 0; rr < 4; rr++) {
        int p = m0 + (lane >> 2) + 8 * rr;
        int gi = i0 + (p >> 4), gj = j0 + (p & 15);
        float pi = 1.0f / (1.0f + expf(logits[gi*2+1] - logits[gi*2]));
        float pj = 1.0f / (1.0f + expf(logits[gj*2+1] - logits[gj*2]));
        c0[rr] = pi * pj;
        c1[rr] = (1.0f - pi) * (1.0f - pj);
        sacc[rr] = 0.0f;
    }

    const float4* epi4 = (const float4*)(SB + OFF_EPI);
#pragma unroll
    for (int nt = 0; nt < 4; nt++)
#pragma unroll
        for (int half = 0; half < 2; half++)
#pragma unroll
            for (int e = 0; e < 2; e++) {
                int col = n0 + nt * 16 + half * 8 + (lane & 3) * 2 + e;
                float4 w = epi4[col];
#pragma unroll
                for (int rr = 0; rr < 4; rr++) {
                    int m2 = rr >> 1;
                    int idx = (rr & 1) * 2 + e;
                    float x = d[m2][nt][half][idx]
                            + c0[rr] * w.x + c1[rr] * w.y + w.z;
                    sacc[rr] = fmaf(gelu_erf(x), w.w, sacc[rr]);
                }
            }

#pragma unroll
    for (int rr = 0; rr < 4; rr++) {
        sacc[rr] += __shfl_xor_sync(0xffffffffu, sacc[rr], 1);
        sacc[rr] += __shfl_xor_sync(0xffffffffu, sacc[rr], 2);
    }
    float* red = (float*)(SB + OFF_RED);
    if ((lane & 3) == 0) {
#pragma unroll
        for (int rr = 0; rr < 4; rr++) {
            int p = m0 + (lane >> 2) + 8 * rr;
            red[p * 4 + ng] = sacc[rr];
        }
    }
    __syncthreads();

    if (tid < 64) {
        int p = tid;
        float4 r4 = *(const float4*)&red[p * 4];
        float tot = (r4.x + r4.y) + (r4.z + r4.w) + b2[0];
        float sc = 1.0f / (1.0f + expf(-tot));
        int gi = i0 + (p >> 4), gj = j0 + (p & 15);
        hs[gi * BN + gj] = sc;
        hs[gj * BN + gi] = sc;
    }
}

// ---------------- row softmax of adj + 5*log(hs + 1e-8) ----------------
__global__ __launch_bounds__(256)
void softmax_kernel(const float* __restrict__ adj,
                    const float* __restrict__ hs,
                    float* __restrict__ out)
{
    const int row = blockIdx.x;
    const int tid = threadIdx.x;
    __shared__ float red[256];

    float v[4];
    float mx = -3.4e38f;
#pragma unroll
    for (int u = 0; u < 4; u++) {
        int j = tid + 256 * u;
        float s = hs[row * BN + j];
        v[u] = adj[row * BN + j] + 5.0f * logf(s + 1e-8f);
        mx = fmaxf(mx, v[u]);
    }
    red[tid] = mx;
    __syncthreads();
    for (int off = 128; off > 0; off >>= 1) {
        if (tid < off) red[tid] = fmaxf(red[tid], red[tid + off]);
        __syncthreads();
    }
    mx = red[0];
    __syncthreads();

    float sum = 0.0f;
#pragma unroll
    for (int u = 0; u < 4; u++) {
        v[u] = expf(v[u] - mx);
        sum += v[u];
    }
    red[tid] = sum;
    __syncthreads();
    for (int off = 128; off > 0; off >>= 1) {
        if (tid < off) red[tid] += red[tid + off];
        __syncthreads();
    }
    float inv = 1.0f / red[0];
#pragma unroll
    for (int u = 0; u < 4; u++) {
        int j = tid + 256 * u;
        out[row * BN + j] = v[u] * inv;
    }
}

extern "C" void kernel_launch(void* const* d_in, const int* in_sizes, int n_in,
                              void* d_out, int out_size)
{
    const float* X      = (const float*)d_in[0];   // [1024, 512]
    const float* logits = (const float*)d_in[1];   // [1024, 2]
    const float* adj    = (const float*)d_in[2];   // [1024, 1024]
    const float* W1     = (const float*)d_in[3];   // [514, 256]
    const float* b1     = (const float*)d_in[4];   // [256]
    const float* W2     = (const float*)d_in[5];   // [256, 1]
    const float* b2     = (const float*)d_in[6];   // [1]

    float* out = (float*)d_out;          // [adj_refined (1M) | h_scores (1M)]
    float* hs  = out + BN * BN;

    static int configured = 0;
    if (!configured) {
        cudaFuncSetAttribute(scorer_mma, cudaFuncAttributeMaxDynamicSharedMemorySize, SMEM_TOTAL);
        configured = 1;
    }

    prep_frag<<<64, 256>>>(W1);
    dim3 grid(BN / TJ, BN / TI);   // (64, 256)
    scorer_mma<<<grid, 256, SMEM_TOTAL>>>(X, logits, b1, W1, W2, b2, hs);
    softmax_kernel<<<BN, 256>>>(adj, hs, out);
}